// round 3
// baseline (speedup 1.0000x reference)
#include <cuda_runtime.h>
#include <math.h>

// Problem constants
#define B 512
#define S 16
#define H 501
#define C 7
#define KP 512          // padded K (inner dim)
#define DEP_OFF 0
#define ENC_OFF (B*S*S) // 131072

// ---------------- device state ----------------
__device__ float g_gs  [B][KP];        // graph state (padded, tail zeros)
__device__ float g_hin [B][KP];        // h_in buffer (padded, tail zeros)
__device__ float g_zpad[B][KP];        // padded z
__device__ float g_WcatT[KP][1024];    // B matrix for K1: [k][2h+e], e=0 gate, e=1 map
__device__ float g_Whh3T[KP][1536];    // B matrix for K2: [k][3h+j], j=r,z,n
__device__ float g_WlinT[KP][KP];      // W_lin1^T padded
__device__ float g_f0[KP];             // sigmoid(b_gate)*b_map
__device__ int   g_cls[B*S];           // argmax of one-hot node encoding
__device__ float g_d[B][S];            // cached dots nhs[j]·we2
__device__ float g_aprev[B];           // cached dot hv·we1

__device__ __forceinline__ float sigm(float x){ return 1.0f/(1.0f+expf(-x)); }

// ---------------- init: transpose/interleave weights, pad z, f0, classes ----------------
__global__ void kinit(const float* __restrict__ Wg, const float* __restrict__ Wm,
                      const float* __restrict__ Whh, const float* __restrict__ Wlin,
                      const float* __restrict__ bgate, const float* __restrict__ bmap,
                      const float* __restrict__ z, const float* __restrict__ ne)
{
    int gt = blockIdx.x*blockDim.x + threadIdx.x;
    int gstep = gridDim.x*blockDim.x;
    for (int i=gt; i<KP*1024; i+=gstep){
        int k = i>>10, n = i & 1023; int h = n>>1, e = n&1;
        float v = 0.f;
        if (k<H && h<H) v = e ? Wm[h*H+k] : Wg[h*H+k];
        (&g_WcatT[0][0])[i] = v;
    }
    for (int i=gt; i<KP*1536; i+=gstep){
        int k = i/1536, n = i%1536; int h = n/3, j = n%3;
        float v = 0.f;
        if (k<H && h<H) v = Whh[(j*H+h)*H + k];
        (&g_Whh3T[0][0])[i] = v;
    }
    for (int i=gt; i<KP*KP; i+=gstep){
        int k = i>>9, h = i & 511;
        float v = 0.f;
        if (k<H && h<H) v = Wlin[h*H+k];
        (&g_WlinT[0][0])[i] = v;
    }
    for (int i=gt; i<B*KP; i+=gstep){
        int b = i>>9, k = i & 511;
        (&g_zpad[0][0])[i] = (k<H) ? z[b*H+k] : 0.f;
    }
    for (int i=gt; i<KP; i+=gstep){
        g_f0[i] = (i<H) ? sigm(bgate[i])*bmap[i] : 0.f;
    }
    for (int i=gt; i<B*S; i+=gstep){
        const float* p = ne + i*C;
        int best = 0; float bv = p[0];
        #pragma unroll
        for (int c=1;c<C;c++){ if (p[c] > bv){ bv = p[c]; best = c; } }
        g_cls[i] = best;
    }
}

// ---------------- shared 64x64 GEMM core: BM=64, BN=64, BK=32, 128 thr, tile 8x4 ----------
__device__ __forceinline__ void gemm_core_64x64(
    const float* __restrict__ A,      // [.. ][KP] row-major, rows m0..m0+63
    const float* __restrict__ Bm,     // [KP][NB] row-major
    int NB, int m0, int n0,
    float acc[8][4], float As[32][72], float Bs[32][64])
{
    int t = threadIdx.x;
    int tx = t & 15, ty = t >> 4;
    int arow = t & 63, ac0 = t >> 6;        // A producer: row, chunk parity
    int bn = (t & 15) * 4, bk0 = t >> 4;    // B producer

    for (int k0 = 0; k0 < KP; k0 += 32){
        #pragma unroll
        for (int r = 0; r < 4; r++){
            int chunk = ac0 + 2*r;          // 0..7
            float4 v = *(const float4*)&A[(size_t)(m0+arow)*KP + k0 + chunk*4];
            As[chunk*4+0][arow] = v.x;
            As[chunk*4+1][arow] = v.y;
            As[chunk*4+2][arow] = v.z;
            As[chunk*4+3][arow] = v.w;
        }
        #pragma unroll
        for (int r = 0; r < 4; r++){
            int k = bk0 + 8*r;
            *(float4*)&Bs[k][bn] = *(const float4*)&Bm[(size_t)(k0+k)*NB + n0 + bn];
        }
        __syncthreads();
        #pragma unroll
        for (int kk = 0; kk < 32; kk++){
            float4 a0 = *(const float4*)&As[kk][ty*8];
            float4 a1 = *(const float4*)&As[kk][ty*8+4];
            float4 b  = *(const float4*)&Bs[kk][tx*4];
            float a[8] = {a0.x,a0.y,a0.z,a0.w,a1.x,a1.y,a1.z,a1.w};
            float bb[4] = {b.x,b.y,b.z,b.w};
            #pragma unroll
            for (int i=0;i<8;i++)
                #pragma unroll
                for (int j=0;j<4;j++) acc[i][j] += a[i]*bb[j];
        }
        __syncthreads();
    }
}

// ---------------- GEMM gs0 = zpad @ WlinT + b_lin1 ; writes g_gs and g_hin ----------------
// grid 64 (8 ntiles x 8 mtiles), 128 thr
__global__ __launch_bounds__(128) void kgemm0(const float* __restrict__ blin)
{
    __shared__ float As[32][72];
    __shared__ float Bs[32][64];
    int nt = blockIdx.x & 7, mt = blockIdx.x >> 3;
    int m0 = mt*64, n0 = nt*64;
    float acc[8][4];
    #pragma unroll
    for (int i=0;i<8;i++)
        #pragma unroll
        for (int j=0;j<4;j++) acc[i][j] = 0.f;
    gemm_core_64x64(&g_zpad[0][0], &g_WlinT[0][0], KP, m0, n0, acc, As, Bs);
    int t = threadIdx.x, tx = t & 15, ty = t >> 4;
    #pragma unroll
    for (int i=0;i<8;i++){
        int m = m0 + ty*8 + i;
        #pragma unroll
        for (int j=0;j<4;j++){
            int h = n0 + tx*4 + j;
            float v = (h<H) ? acc[i][j] + blin[h] : 0.f;
            g_gs[m][h] = v;
            g_hin[m][h] = v;
        }
    }
}

// ---------------- fused: [gemm1(idx) | vert(idx) | edge(idx-1)] -----------------
// all parts read the SAME g_gs snapshot; gemm writes g_hin, vert/edge write out + caches
__global__ __launch_bounds__(128) void kfused1(
    const float* __restrict__ dep, const float* __restrict__ bgate,
    const float* __restrict__ bmap, const float* __restrict__ Wv,
    const float* __restrict__ bv, const float* __restrict__ We,
    const float* __restrict__ be, float* __restrict__ out, int idx)
{
    __shared__ float As[32][72];
    __shared__ float Bs[32][64];
    int gemmBlocks = (idx >= 1) ? 128 : 0;
    int bid = blockIdx.x;
    int t = threadIdx.x;

    if (bid < gemmBlocks){
        // ---- GEMM1: GM = gs @ WcatT, epilogue -> g_hin ----
        int nt = bid & 15, mt = bid >> 4;
        int m0 = mt*64, n0 = nt*64;
        float acc[8][4];
        #pragma unroll
        for (int i=0;i<8;i++)
            #pragma unroll
            for (int j=0;j<4;j++) acc[i][j] = 0.f;
        gemm_core_64x64(&g_gs[0][0], &g_WcatT[0][0], 1024, m0, n0, acc, As, Bs);
        int tx = t & 15, ty = t >> 4;
        int hbase = (n0>>1) + tx*2;
        #pragma unroll
        for (int i=0;i<8;i++){
            int m = m0 + ty*8 + i;
            float rb = dep[m*(S*S) + idx*S + (idx-1)];
            #pragma unroll
            for (int p=0;p<2;p++){
                int h = hbase + p;
                float val = 0.f;
                if (h < H){
                    float f0 = g_f0[h];
                    float fv = (rb != 0.f)
                        ? sigm(acc[i][2*p] + bgate[h]) * (acc[i][2*p+1] + bmap[h])
                        : f0;
                    val = 15.f*f0 + fv;
                }
                g_hin[m][h] = val;
            }
        }
        return;
    }

    float* red = &As[0][0];
    int r = bid - gemmBlocks;
    if (r < 512){
        // ---- vertex logits + softmax for idx, b = r ----
        int b = r;
        int w = t >> 5, lane = t & 31;
        float sA = 0.f, sB = 0.f;
        for (int k = lane; k < H; k += 32){
            float g = g_gs[b][k];
            sA += g * Wv[w*H + k];
            if (w < 3) sB += g * Wv[(4+w)*H + k];
        }
        #pragma unroll
        for (int o=16;o>0;o>>=1){
            sA += __shfl_down_sync(0xffffffffu, sA, o);
            sB += __shfl_down_sync(0xffffffffu, sB, o);
        }
        if (lane == 0){
            red[w] = sA + bv[w];
            if (w < 3) red[4+w] = sB + bv[4+w];
        }
        __syncthreads();
        if (t == 0){
            float mx = red[0];
            #pragma unroll
            for (int c=1;c<C;c++) mx = fmaxf(mx, red[c]);
            float e[C]; float sum = 0.f;
            #pragma unroll
            for (int c=0;c<C;c++){ e[c] = expf(red[c]-mx); sum += e[c]; }
            float inv = 1.f/sum;
            float* o = out + ENC_OFF + (b*S + idx)*C;
            #pragma unroll
            for (int c=0;c<C;c++) o[c] = e[c]*inv;
        }
    } else {
        // ---- edge row for eidx = idx-1, b = r-512 (only launched when idx>=1) ----
        int b = r - 512;
        int eidx = idx - 1;
        int w = t >> 5, lane = t & 31;
        float s1 = 0.f, s2 = 0.f;
        for (int k = t; k < H; k += 128){
            float g = g_gs[b][k];
            s1 += g * We[k];
            s2 += g * We[H + k];
        }
        #pragma unroll
        for (int o=16;o>0;o>>=1){
            s1 += __shfl_down_sync(0xffffffffu, s1, o);
            s2 += __shfl_down_sync(0xffffffffu, s2, o);
        }
        if (lane == 0){ red[w] = s1; red[8+w] = s2; }
        __syncthreads();
        if (t == 0){
            float a_new = 0.f, d_new = 0.f;
            #pragma unroll
            for (int i=0;i<4;i++){ a_new += red[i]; d_new += red[8+i]; }
            float bev = be[0];
            float a_old = g_aprev[b];
            float* row = out + DEP_OFF + (b*S + eidx)*S;
            #pragma unroll
            for (int col=0; col<S; col++){
                float v;
                if (col >= eidx) v = 0.f;
                else if (col == eidx-1) v = (a_old + g_d[b][eidx-1] + bev >= 0.f) ? 1.f : 0.f;
                else v = (a_new + g_d[b][col] + bev >= 0.f) ? 1.f : 0.f;
                row[col] = v;
            }
            g_d[b][eidx] = d_new;
            g_aprev[b] = a_new;
        }
    }
}

// ---------------- K2: gh = h_in @ Whh3T, GRU epilogue -> g_gs ----------------
// grid 256 (32 ntiles x 8 mtiles), 128 thr, BM=64 BN=48 BK=32, tile 8x3
__global__ __launch_bounds__(128) void kgemm2(const float* __restrict__ Wih,
                                              const float* __restrict__ bih,
                                              const float* __restrict__ bhh, int idx)
{
    __shared__ float As[32][72];
    __shared__ float Bs[32][48];
    int bid = blockIdx.x;
    int nt = bid & 31, mt = bid >> 5;
    int m0 = mt*64, n0 = nt*48;
    int t = threadIdx.x, tx = t & 15, ty = t >> 4;
    int arow = t & 63, ac0 = t >> 6;
    float acc[8][3];
    #pragma unroll
    for (int i=0;i<8;i++)
        #pragma unroll
        for (int j=0;j<3;j++) acc[i][j] = 0.f;

    for (int k0 = 0; k0 < KP; k0 += 32){
        #pragma unroll
        for (int r = 0; r < 4; r++){
            int chunk = ac0 + 2*r;
            float4 v = *(const float4*)&g_hin[m0+arow][k0 + chunk*4];
            As[chunk*4+0][arow] = v.x;
            As[chunk*4+1][arow] = v.y;
            As[chunk*4+2][arow] = v.z;
            As[chunk*4+3][arow] = v.w;
        }
        #pragma unroll
        for (int r = 0; r < 3; r++){
            int i4 = t + 128*r;           // 0..383 float4 slots
            int kr = i4 / 12, c4 = i4 % 12;
            *(float4*)&Bs[kr][c4*4] = *(const float4*)&g_Whh3T[k0+kr][n0 + c4*4];
        }
        __syncthreads();
        #pragma unroll
        for (int kk = 0; kk < 32; kk++){
            float4 a0 = *(const float4*)&As[kk][ty*8];
            float4 a1 = *(const float4*)&As[kk][ty*8+4];
            float b0 = Bs[kk][tx*3+0];
            float b1 = Bs[kk][tx*3+1];
            float b2 = Bs[kk][tx*3+2];
            float a[8] = {a0.x,a0.y,a0.z,a0.w,a1.x,a1.y,a1.z,a1.w};
            #pragma unroll
            for (int i=0;i<8;i++){
                acc[i][0] += a[i]*b0;
                acc[i][1] += a[i]*b1;
                acc[i][2] += a[i]*b2;
            }
        }
        __syncthreads();
    }
    int h = nt*16 + tx;
    if (h < H){
        #pragma unroll
        for (int i=0;i<8;i++){
            int m = m0 + ty*8 + i;
            int c = g_cls[m*S + idx];
            float gh_r = acc[i][0] + bhh[h];
            float gh_z = acc[i][1] + bhh[H+h];
            float gh_n = acc[i][2] + bhh[2*H+h];
            float gi_r = Wih[(      h)*C + c] + bih[h];
            float gi_z = Wih[(H   + h)*C + c] + bih[H+h];
            float gi_n = Wih[(2*H + h)*C + c] + bih[2*H+h];
            float rr = sigm(gi_r + gh_r);
            float u  = sigm(gi_z + gh_z);
            float nn = tanhf(gi_n + rr*gh_n);
            float hv = (1.f-u)*nn + u*g_hin[m][h];
            g_gs[m][h] = hv;
        }
    }
}

// ---------------- final edge row (idx = S-1) ----------------
__global__ __launch_bounds__(128) void kedge_final(const float* __restrict__ We,
                                                   const float* __restrict__ be,
                                                   float* __restrict__ out)
{
    __shared__ float red[16];
    int b = blockIdx.x;
    int t = threadIdx.x;
    int w = t >> 5, lane = t & 31;
    const int eidx = S - 1;
    float s1 = 0.f, s2 = 0.f;
    for (int k = t; k < H; k += 128){
        float g = g_gs[b][k];
        s1 += g * We[k];
        s2 += g * We[H + k];
    }
    #pragma unroll
    for (int o=16;o>0;o>>=1){
        s1 += __shfl_down_sync(0xffffffffu, s1, o);
        s2 += __shfl_down_sync(0xffffffffu, s2, o);
    }
    if (lane == 0){ red[w] = s1; red[8+w] = s2; }
    __syncthreads();
    if (t == 0){
        float a_new = 0.f;
        #pragma unroll
        for (int i=0;i<4;i++) a_new += red[i];
        float bev = be[0];
        float a_old = g_aprev[b];
        float* row = out + DEP_OFF + (b*S + eidx)*S;
        #pragma unroll
        for (int col=0; col<S; col++){
            float v;
            if (col >= eidx) v = 0.f;
            else if (col == eidx-1) v = (a_old + g_d[b][eidx-1] + bev >= 0.f) ? 1.f : 0.f;
            else v = (a_new + g_d[b][col] + bev >= 0.f) ? 1.f : 0.f;
            row[col] = v;
        }
    }
}

// ---------------- launch ----------------
extern "C" void kernel_launch(void* const* d_in, const int* in_sizes, int n_in,
                              void* d_out, int out_size)
{
    const float* z     = (const float*)d_in[0];
    const float* dep   = (const float*)d_in[1];
    const float* ne    = (const float*)d_in[2];
    const float* Wlin  = (const float*)d_in[3];
    const float* blin  = (const float*)d_in[4];
    const float* Wv    = (const float*)d_in[5];
    const float* bv    = (const float*)d_in[6];
    const float* We    = (const float*)d_in[7];
    const float* be    = (const float*)d_in[8];
    const float* Wg    = (const float*)d_in[9];
    const float* bgate = (const float*)d_in[10];
    const float* Wm    = (const float*)d_in[11];
    const float* bmap  = (const float*)d_in[12];
    const float* Wih   = (const float*)d_in[13];
    const float* bih   = (const float*)d_in[14];
    const float* Whh   = (const float*)d_in[15];
    const float* bhh   = (const float*)d_in[16];
    float* out = (float*)d_out;

    kinit<<<1024, 256>>>(Wg, Wm, Whh, Wlin, bgate, bmap, z, ne);
    kgemm0<<<64, 128>>>(blin);
    for (int idx=0; idx<S; ++idx){
        int grid = (idx >= 1) ? (128 + 512 + 512) : 512;
        kfused1<<<grid, 128>>>(dep, bgate, bmap, Wv, bv, We, be, out, idx);
        kgemm2<<<256, 128>>>(Wih, bih, bhh, idx);
    }
    kedge_final<<<B, 128>>>(We, be, out);
    (void)in_sizes; (void)n_in; (void)out_size;
}